// round 6
// baseline (speedup 1.0000x reference)
#include <cuda_runtime.h>
#include <cstdint>
#include <cfloat>

#define C_CL   8
#define E_EX   8
#define D_DIM  4096
#define NU2    (D_DIM / 4)     // row length in ulonglong2 (16B) units = 1024
#define NTOT   (C_CL * E_EX)
#define MAX_T  8192

// Scratch (no allocs allowed)
__device__ int g_cnt[C_CL];
__device__ int g_cluster[MAX_T];
__device__ int g_bucket[C_CL * MAX_T];
__device__ int g_order[MAX_T];

__global__ void zero_cnt_kernel() {
    if (threadIdx.x < C_CL) g_cnt[threadIdx.x] = 0;
}

// expert_ids robust read (int32 vs int64 delivery; content = arange(64))
__device__ __forceinline__ int read_eid(const void* p, int i) {
    const int* p32 = (const int*)p;
    if (__ldg(p32 + 1) == 0) return (int)__ldg(((const long long*)p) + i);
    return __ldg(p32 + i);
}

// ---- packed f32x2 helpers ----
__device__ __forceinline__ unsigned long long fma2(unsigned long long a,
                                                   unsigned long long b,
                                                   unsigned long long c) {
    unsigned long long d;
    asm("fma.rn.f32x2 %0, %1, %2, %3;" : "=l"(d) : "l"(a), "l"(b), "l"(c));
    return d;
}
__device__ __forceinline__ float sum2(unsigned long long v) {
    return __uint_as_float((unsigned)(v & 0xffffffffull)) +
           __uint_as_float((unsigned)(v >> 32));
}

// ============================================================================
// Pass A: cluster logits + argmax + bucket scatter.
// Block = 256 thr = 8 warps = 4 token-quads x 2 D-splits. Warp: 4 tokens x
// 2048 dims. Per iter (128 dims): 4 dense x-LDG.128 + 8 dense Wc-LDG.128,
// 64 FFMA2 into acc[8][4]. All loads dense -> no wavefront replication.
// ============================================================================
__global__ void __launch_bounds__(256, 2) cluster_kernel(
    const float* __restrict__ x,
    const float* __restrict__ Wc)
{
    __shared__ float s_part[2][4][4][8];   // [split][quad][t][c]

    const int w    = threadIdx.x >> 5;
    const int lane = threadIdx.x & 31;
    const int qi   = w >> 1;               // token quad (0..3)
    const int s    = w & 1;                // D-split (0..1)
    const int tbase = blockIdx.x * 16 + qi * 4;

    const ulonglong2* xr0 = reinterpret_cast<const ulonglong2*>(x + (size_t)(tbase + 0) * D_DIM);
    const ulonglong2* xr1 = reinterpret_cast<const ulonglong2*>(x + (size_t)(tbase + 1) * D_DIM);
    const ulonglong2* xr2 = reinterpret_cast<const ulonglong2*>(x + (size_t)(tbase + 2) * D_DIM);
    const ulonglong2* xr3 = reinterpret_cast<const ulonglong2*>(x + (size_t)(tbase + 3) * D_DIM);
    const ulonglong2* wr  = reinterpret_cast<const ulonglong2*>(Wc);

    unsigned long long acc[C_CL][4];
#pragma unroll
    for (int c = 0; c < C_CL; ++c)
#pragma unroll
        for (int t = 0; t < 4; ++t) acc[c][t] = 0ull;

    for (int it = 0; it < 16; ++it) {
        const int idx = s * 512 + it * 32 + lane;   // ull2 index into a row
        ulonglong2 x0 = __ldg(xr0 + idx);
        ulonglong2 x1 = __ldg(xr1 + idx);
        ulonglong2 x2 = __ldg(xr2 + idx);
        ulonglong2 x3 = __ldg(xr3 + idx);
#pragma unroll
        for (int c = 0; c < C_CL; ++c) {
            ulonglong2 wv = __ldg(wr + c * NU2 + idx);
            acc[c][0] = fma2(x0.x, wv.x, acc[c][0]);
            acc[c][0] = fma2(x0.y, wv.y, acc[c][0]);
            acc[c][1] = fma2(x1.x, wv.x, acc[c][1]);
            acc[c][1] = fma2(x1.y, wv.y, acc[c][1]);
            acc[c][2] = fma2(x2.x, wv.x, acc[c][2]);
            acc[c][2] = fma2(x2.y, wv.y, acc[c][2]);
            acc[c][3] = fma2(x3.x, wv.x, acc[c][3]);
            acc[c][3] = fma2(x3.y, wv.y, acc[c][3]);
        }
    }

    // Reduce each of the 32 (c,t) partials across the full warp.
    float r[C_CL][4];
#pragma unroll
    for (int c = 0; c < C_CL; ++c)
#pragma unroll
        for (int t = 0; t < 4; ++t) r[c][t] = sum2(acc[c][t]);
#pragma unroll
    for (int d = 16; d >= 1; d >>= 1)
#pragma unroll
        for (int c = 0; c < C_CL; ++c)
#pragma unroll
            for (int t = 0; t < 4; ++t)
                r[c][t] += __shfl_xor_sync(0xffffffffu, r[c][t], d);

#pragma unroll
    for (int c = 0; c < C_CL; ++c)
#pragma unroll
        for (int t = 0; t < 4; ++t)
            if (lane == c * 4 + t) s_part[s][qi][t][c] = r[c][t];
    __syncthreads();

    // Combine 2 splits + argmax: 128 threads = 16 tok x 8 c.
    if (threadIdx.x < 128) {
        const int tl = threadIdx.x >> 3;    // token-local 0..15
        const int c  = threadIdx.x & 7;
        const int quad = tl >> 2, tt = tl & 3;
        float v = s_part[0][quad][tt][c] + s_part[1][quad][tt][c];
        int bi = c;
#pragma unroll
        for (int d = 1; d <= 4; d <<= 1) {
            float vo = __shfl_xor_sync(0xffffffffu, v, d);
            int   io = __shfl_xor_sync(0xffffffffu, bi, d);
            if (vo > v || (vo == v && io < bi)) { v = vo; bi = io; }  // first-max
        }
        if (c == 0) {
            const int t = blockIdx.x * 16 + tl;
            g_cluster[t] = bi;
            int pos = atomicAdd(&g_cnt[bi], 1);
            g_bucket[bi * MAX_T + pos] = t;
        }
    }
}

// ============================================================================
// Middle: compact gapped buckets into cluster-major flat order.
// ============================================================================
__global__ void __launch_bounds__(256) order_kernel() {
    __shared__ int base[C_CL];
    if (threadIdx.x == 0) {
        int b = 0;
        for (int c = 0; c < C_CL; ++c) { base[c] = b; b += g_cnt[c]; }
    }
    __syncthreads();
    for (int c = 0; c < C_CL; ++c) {
        const int n = g_cnt[c];
        const int b = base[c];
        for (int i = threadIdx.x; i < n; i += 256)
            g_order[b + i] = g_bucket[c * MAX_T + i];
    }
}

// ============================================================================
// Pass B: expert logits for selected cluster + scatter into output row.
// Same dense outer-product structure; quads taken cluster-major from g_order
// so the 4 tokens of a quad share expert weights (fast path). Boundary quads
// (<8 of 2048) take the per-token slow path.
// ============================================================================
__global__ void __launch_bounds__(256, 2) expert_kernel(
    const float* __restrict__ x,
    const float* __restrict__ We,
    const void* __restrict__ eids,
    float* __restrict__ out)
{
    __shared__ float s_part[2][4][4][8];   // [split][quad][t][e]
    __shared__ float s_logit[16][8];
    __shared__ int   s_eid[16][8];
    __shared__ int   s_tok[16];
    __shared__ int   s_cl[16];

    const int w    = threadIdx.x >> 5;
    const int lane = threadIdx.x & 31;
    const int qi   = w >> 1;
    const int s    = w & 1;
    const int pbase = blockIdx.x * 16 + qi * 4;

    const int t0 = __ldg(&g_order[pbase + 0]);
    const int t1 = __ldg(&g_order[pbase + 1]);
    const int t2 = __ldg(&g_order[pbase + 2]);
    const int t3 = __ldg(&g_order[pbase + 3]);
    const int c0 = g_cluster[t0], c1 = g_cluster[t1];
    const int c2 = g_cluster[t2], c3 = g_cluster[t3];
    if (s == 0 && lane == 0) {
        s_tok[qi * 4 + 0] = t0; s_cl[qi * 4 + 0] = c0;
        s_tok[qi * 4 + 1] = t1; s_cl[qi * 4 + 1] = c1;
        s_tok[qi * 4 + 2] = t2; s_cl[qi * 4 + 2] = c2;
        s_tok[qi * 4 + 3] = t3; s_cl[qi * 4 + 3] = c3;
    }

    const ulonglong2* xr0 = reinterpret_cast<const ulonglong2*>(x + (size_t)t0 * D_DIM);
    const ulonglong2* xr1 = reinterpret_cast<const ulonglong2*>(x + (size_t)t1 * D_DIM);
    const ulonglong2* xr2 = reinterpret_cast<const ulonglong2*>(x + (size_t)t2 * D_DIM);
    const ulonglong2* xr3 = reinterpret_cast<const ulonglong2*>(x + (size_t)t3 * D_DIM);

    unsigned long long acc[E_EX][4];
#pragma unroll
    for (int e = 0; e < E_EX; ++e)
#pragma unroll
        for (int t = 0; t < 4; ++t) acc[e][t] = 0ull;

    if (c0 == c1 && c1 == c2 && c2 == c3) {
        // Fast path: one weight base for the whole quad.
        const ulonglong2* wr = reinterpret_cast<const ulonglong2*>(
            We + (size_t)c0 * (E_EX * D_DIM));
        for (int it = 0; it < 16; ++it) {
            const int idx = s * 512 + it * 32 + lane;
            ulonglong2 x0 = __ldg(xr0 + idx);
            ulonglong2 x1 = __ldg(xr1 + idx);
            ulonglong2 x2 = __ldg(xr2 + idx);
            ulonglong2 x3 = __ldg(xr3 + idx);
#pragma unroll
            for (int e = 0; e < E_EX; ++e) {
                ulonglong2 wv = __ldg(wr + e * NU2 + idx);
                acc[e][0] = fma2(x0.x, wv.x, acc[e][0]);
                acc[e][0] = fma2(x0.y, wv.y, acc[e][0]);
                acc[e][1] = fma2(x1.x, wv.x, acc[e][1]);
                acc[e][1] = fma2(x1.y, wv.y, acc[e][1]);
                acc[e][2] = fma2(x2.x, wv.x, acc[e][2]);
                acc[e][2] = fma2(x2.y, wv.y, acc[e][2]);
                acc[e][3] = fma2(x3.x, wv.x, acc[e][3]);
                acc[e][3] = fma2(x3.y, wv.y, acc[e][3]);
            }
        }
    } else {
        // Slow path: per-token weight bases (rare boundary quads).
        const ulonglong2* w0 = reinterpret_cast<const ulonglong2*>(We + (size_t)c0 * (E_EX * D_DIM));
        const ulonglong2* w1 = reinterpret_cast<const ulonglong2*>(We + (size_t)c1 * (E_EX * D_DIM));
        const ulonglong2* w2 = reinterpret_cast<const ulonglong2*>(We + (size_t)c2 * (E_EX * D_DIM));
        const ulonglong2* w3 = reinterpret_cast<const ulonglong2*>(We + (size_t)c3 * (E_EX * D_DIM));
        for (int it = 0; it < 16; ++it) {
            const int idx = s * 512 + it * 32 + lane;
            ulonglong2 x0 = __ldg(xr0 + idx);
            ulonglong2 x1 = __ldg(xr1 + idx);
            ulonglong2 x2 = __ldg(xr2 + idx);
            ulonglong2 x3 = __ldg(xr3 + idx);
#pragma unroll
            for (int e = 0; e < E_EX; ++e) {
                ulonglong2 a0 = __ldg(w0 + e * NU2 + idx);
                ulonglong2 a1 = __ldg(w1 + e * NU2 + idx);
                ulonglong2 a2 = __ldg(w2 + e * NU2 + idx);
                ulonglong2 a3 = __ldg(w3 + e * NU2 + idx);
                acc[e][0] = fma2(x0.x, a0.x, acc[e][0]);
                acc[e][0] = fma2(x0.y, a0.y, acc[e][0]);
                acc[e][1] = fma2(x1.x, a1.x, acc[e][1]);
                acc[e][1] = fma2(x1.y, a1.y, acc[e][1]);
                acc[e][2] = fma2(x2.x, a2.x, acc[e][2]);
                acc[e][2] = fma2(x2.y, a2.y, acc[e][2]);
                acc[e][3] = fma2(x3.x, a3.x, acc[e][3]);
                acc[e][3] = fma2(x3.y, a3.y, acc[e][3]);
            }
        }
    }

    float r[E_EX][4];
#pragma unroll
    for (int e = 0; e < E_EX; ++e)
#pragma unroll
        for (int t = 0; t < 4; ++t) r[e][t] = sum2(acc[e][t]);
#pragma unroll
    for (int d = 16; d >= 1; d >>= 1)
#pragma unroll
        for (int e = 0; e < E_EX; ++e)
#pragma unroll
            for (int t = 0; t < 4; ++t)
                r[e][t] += __shfl_xor_sync(0xffffffffu, r[e][t], d);

#pragma unroll
    for (int e = 0; e < E_EX; ++e)
#pragma unroll
        for (int t = 0; t < 4; ++t)
            if (lane == e * 4 + t) s_part[s][qi][t][e] = r[e][t];
    __syncthreads();

    // Combine splits + fetch expert ids: 128 threads = 16 tok x 8 e.
    if (threadIdx.x < 128) {
        const int tl = threadIdx.x >> 3;
        const int e  = threadIdx.x & 7;
        const int quad = tl >> 2, tt = tl & 3;
        s_logit[tl][e] = s_part[0][quad][tt][e] + s_part[1][quad][tt][e];
        s_eid[tl][e]   = read_eid(eids, s_cl[tl] * E_EX + e);
    }
    __syncthreads();

    // Scatter: 256 threads = 16 tokens x 16 float4 (full 64-col rows).
    {
        const int tl = threadIdx.x >> 4;
        const int q  = threadIdx.x & 15;
        const int tok = s_tok[tl];
        float v[4];
#pragma unroll
        for (int j = 0; j < 4; ++j) {
            const int col = q * 4 + j;
            float val = -FLT_MAX;              // == jnp.finfo(float32).min
#pragma unroll
            for (int e = 0; e < E_EX; ++e)
                val = (s_eid[tl][e] == col) ? s_logit[tl][e] : val;
            v[j] = val;
        }
        reinterpret_cast<float4*>(out + (size_t)tok * NTOT)[q] =
            make_float4(v[0], v[1], v[2], v[3]);
    }
}

extern "C" void kernel_launch(void* const* d_in, const int* in_sizes, int n_in,
                              void* d_out, int out_size) {
    const float* x    = (const float*)d_in[0];
    const float* Wc   = (const float*)d_in[1];
    const float* We   = (const float*)d_in[2];
    const void*  eids = d_in[3];
    float*       out  = (float*)d_out;

    const int D = in_sizes[2] / in_sizes[3];     // 4096
    const int T = in_sizes[0] / D;               // 8192
    (void)n_in; (void)out_size;

    zero_cnt_kernel<<<1, 32>>>();

    const int blocks = T / 16;           // 16 tokens per block
    cluster_kernel<<<blocks, 256>>>(x, Wc);
    order_kernel<<<1, 256>>>();
    expert_kernel<<<blocks, 256>>>(x, We, eids, out);
}

// round 7
// speedup vs baseline: 1.2291x; 1.2291x over previous
#include <cuda_runtime.h>
#include <cstdint>
#include <cfloat>

#define C_CL   8
#define E_EX   8
#define D_DIM  4096
#define NU2    (D_DIM / 4)     // row length in ulonglong2 (16B) units = 1024
#define NTOT   (C_CL * E_EX)
#define MAX_T  8192

// Scratch (no allocs allowed)
__device__ int g_cnt[C_CL];
__device__ int g_cluster[MAX_T];
__device__ int g_bucket[C_CL * MAX_T];
__device__ int g_order[MAX_T];

__global__ void zero_cnt_kernel() {
    if (threadIdx.x < C_CL) g_cnt[threadIdx.x] = 0;
}

// expert_ids robust read (int32 vs int64 delivery; content = arange(64))
__device__ __forceinline__ int read_eid(const void* p, int i) {
    const int* p32 = (const int*)p;
    if (__ldg(p32 + 1) == 0) return (int)__ldg(((const long long*)p) + i);
    return __ldg(p32 + i);
}

// ---- packed f32x2 helpers ----
__device__ __forceinline__ unsigned long long fma2(unsigned long long a,
                                                   unsigned long long b,
                                                   unsigned long long c) {
    unsigned long long d;
    asm("fma.rn.f32x2 %0, %1, %2, %3;" : "=l"(d) : "l"(a), "l"(b), "l"(c));
    return d;
}
__device__ __forceinline__ float sum2(unsigned long long v) {
    return __uint_as_float((unsigned)(v & 0xffffffffull)) +
           __uint_as_float((unsigned)(v >> 32));
}

// ============================================================================
// Pass A: cluster logits + argmax + bucket scatter.
// Block = 8 warps = 4 token-quads x 2 D-splits. Warp: 4 tokens x 2048 dims,
// dense LDG.128 outer product with one-deep x prefetch: next iteration's
// 4 x-lines (the DRAM stream) are in flight while this iteration's 8 weight
// loads (L1/L2-hot) + 64 FFMA2 issue.
// ============================================================================
__global__ void __launch_bounds__(256, 2) cluster_kernel(
    const float* __restrict__ x,
    const float* __restrict__ Wc)
{
    __shared__ float s_part[2][4][4][8];   // [split][quad][t][c]

    const int w    = threadIdx.x >> 5;
    const int lane = threadIdx.x & 31;
    const int qi   = w >> 1;               // token quad (0..3)
    const int s    = w & 1;                // D-split (0..1)
    const int tbase = blockIdx.x * 16 + qi * 4;

    const ulonglong2* xr0 = reinterpret_cast<const ulonglong2*>(x + (size_t)(tbase + 0) * D_DIM);
    const ulonglong2* xr1 = reinterpret_cast<const ulonglong2*>(x + (size_t)(tbase + 1) * D_DIM);
    const ulonglong2* xr2 = reinterpret_cast<const ulonglong2*>(x + (size_t)(tbase + 2) * D_DIM);
    const ulonglong2* xr3 = reinterpret_cast<const ulonglong2*>(x + (size_t)(tbase + 3) * D_DIM);
    const ulonglong2* wr  = reinterpret_cast<const ulonglong2*>(Wc);

    unsigned long long acc[C_CL][4];
#pragma unroll
    for (int c = 0; c < C_CL; ++c)
#pragma unroll
        for (int t = 0; t < 4; ++t) acc[c][t] = 0ull;

    int idx = s * 512 + lane;
    ulonglong2 x0 = __ldg(xr0 + idx);
    ulonglong2 x1 = __ldg(xr1 + idx);
    ulonglong2 x2 = __ldg(xr2 + idx);
    ulonglong2 x3 = __ldg(xr3 + idx);

    for (int it = 0; it < 16; ++it) {
        const int nidx = idx + ((it < 15) ? 32 : 0);
        ulonglong2 n0 = __ldg(xr0 + nidx);
        ulonglong2 n1 = __ldg(xr1 + nidx);
        ulonglong2 n2 = __ldg(xr2 + nidx);
        ulonglong2 n3 = __ldg(xr3 + nidx);
#pragma unroll
        for (int c = 0; c < C_CL; ++c) {
            ulonglong2 wv = __ldg(wr + c * NU2 + idx);
            acc[c][0] = fma2(x0.x, wv.x, acc[c][0]);
            acc[c][0] = fma2(x0.y, wv.y, acc[c][0]);
            acc[c][1] = fma2(x1.x, wv.x, acc[c][1]);
            acc[c][1] = fma2(x1.y, wv.y, acc[c][1]);
            acc[c][2] = fma2(x2.x, wv.x, acc[c][2]);
            acc[c][2] = fma2(x2.y, wv.y, acc[c][2]);
            acc[c][3] = fma2(x3.x, wv.x, acc[c][3]);
            acc[c][3] = fma2(x3.y, wv.y, acc[c][3]);
        }
        x0 = n0; x1 = n1; x2 = n2; x3 = n3;
        idx = nidx;
    }

    // Reduce c-by-c (keeps epilogue register pressure at ~4 live floats).
#pragma unroll
    for (int c = 0; c < C_CL; ++c) {
        float r0 = sum2(acc[c][0]), r1 = sum2(acc[c][1]);
        float r2 = sum2(acc[c][2]), r3 = sum2(acc[c][3]);
#pragma unroll
        for (int d = 16; d >= 1; d >>= 1) {
            r0 += __shfl_xor_sync(0xffffffffu, r0, d);
            r1 += __shfl_xor_sync(0xffffffffu, r1, d);
            r2 += __shfl_xor_sync(0xffffffffu, r2, d);
            r3 += __shfl_xor_sync(0xffffffffu, r3, d);
        }
        if (lane == c * 4 + 0) s_part[s][qi][0][c] = r0;
        if (lane == c * 4 + 1) s_part[s][qi][1][c] = r1;
        if (lane == c * 4 + 2) s_part[s][qi][2][c] = r2;
        if (lane == c * 4 + 3) s_part[s][qi][3][c] = r3;
    }
    __syncthreads();

    // Combine 2 splits + argmax: 128 threads = 16 tok x 8 c.
    if (threadIdx.x < 128) {
        const int tl = threadIdx.x >> 3;    // token-local 0..15
        const int c  = threadIdx.x & 7;
        const int quad = tl >> 2, tt = tl & 3;
        float v = s_part[0][quad][tt][c] + s_part[1][quad][tt][c];
        int bi = c;
#pragma unroll
        for (int d = 1; d <= 4; d <<= 1) {
            float vo = __shfl_xor_sync(0xffffffffu, v, d);
            int   io = __shfl_xor_sync(0xffffffffu, bi, d);
            if (vo > v || (vo == v && io < bi)) { v = vo; bi = io; }  // first-max
        }
        if (c == 0) {
            const int t = blockIdx.x * 16 + tl;
            g_cluster[t] = bi;
            int pos = atomicAdd(&g_cnt[bi], 1);
            g_bucket[bi * MAX_T + pos] = t;
        }
    }
}

// ============================================================================
// Middle: compact gapped buckets into cluster-major flat order (8 blocks).
// ============================================================================
__global__ void __launch_bounds__(256) order_kernel() {
    const int c = blockIdx.x;
    int b = 0;
    for (int cc = 0; cc < c; ++cc) b += g_cnt[cc];
    const int n = g_cnt[c];
    for (int i = threadIdx.x; i < n; i += 256)
        g_order[b + i] = g_bucket[c * MAX_T + i];
}

// ============================================================================
// Pass B: expert logits for selected cluster + scatter into output row.
// Same dense outer-product + prefetch structure; quads taken cluster-major
// from g_order so the 4 tokens of a quad share expert weights (fast path).
// ============================================================================
__global__ void __launch_bounds__(256, 2) expert_kernel(
    const float* __restrict__ x,
    const float* __restrict__ We,
    const void* __restrict__ eids,
    float* __restrict__ out)
{
    __shared__ float s_part[2][4][4][8];   // [split][quad][t][e]
    __shared__ float s_logit[16][8];
    __shared__ int   s_eid[16][8];
    __shared__ int   s_tok[16];
    __shared__ int   s_cl[16];

    const int w    = threadIdx.x >> 5;
    const int lane = threadIdx.x & 31;
    const int qi   = w >> 1;
    const int s    = w & 1;
    const int pbase = blockIdx.x * 16 + qi * 4;

    const int t0 = __ldg(&g_order[pbase + 0]);
    const int t1 = __ldg(&g_order[pbase + 1]);
    const int t2 = __ldg(&g_order[pbase + 2]);
    const int t3 = __ldg(&g_order[pbase + 3]);
    const int c0 = g_cluster[t0], c1 = g_cluster[t1];
    const int c2 = g_cluster[t2], c3 = g_cluster[t3];
    if (s == 0 && lane == 0) {
        s_tok[qi * 4 + 0] = t0; s_cl[qi * 4 + 0] = c0;
        s_tok[qi * 4 + 1] = t1; s_cl[qi * 4 + 1] = c1;
        s_tok[qi * 4 + 2] = t2; s_cl[qi * 4 + 2] = c2;
        s_tok[qi * 4 + 3] = t3; s_cl[qi * 4 + 3] = c3;
    }

    const ulonglong2* xr0 = reinterpret_cast<const ulonglong2*>(x + (size_t)t0 * D_DIM);
    const ulonglong2* xr1 = reinterpret_cast<const ulonglong2*>(x + (size_t)t1 * D_DIM);
    const ulonglong2* xr2 = reinterpret_cast<const ulonglong2*>(x + (size_t)t2 * D_DIM);
    const ulonglong2* xr3 = reinterpret_cast<const ulonglong2*>(x + (size_t)t3 * D_DIM);

    unsigned long long acc[E_EX][4];
#pragma unroll
    for (int e = 0; e < E_EX; ++e)
#pragma unroll
        for (int t = 0; t < 4; ++t) acc[e][t] = 0ull;

    if (c0 == c1 && c1 == c2 && c2 == c3) {
        // Fast path: one weight base for the whole quad; x prefetched 1 deep.
        const ulonglong2* wr = reinterpret_cast<const ulonglong2*>(
            We + (size_t)c0 * (E_EX * D_DIM));
        int idx = s * 512 + lane;
        ulonglong2 x0 = __ldg(xr0 + idx);
        ulonglong2 x1 = __ldg(xr1 + idx);
        ulonglong2 x2 = __ldg(xr2 + idx);
        ulonglong2 x3 = __ldg(xr3 + idx);
        for (int it = 0; it < 16; ++it) {
            const int nidx = idx + ((it < 15) ? 32 : 0);
            ulonglong2 n0 = __ldg(xr0 + nidx);
            ulonglong2 n1 = __ldg(xr1 + nidx);
            ulonglong2 n2 = __ldg(xr2 + nidx);
            ulonglong2 n3 = __ldg(xr3 + nidx);
#pragma unroll
            for (int e = 0; e < E_EX; ++e) {
                ulonglong2 wv = __ldg(wr + e * NU2 + idx);
                acc[e][0] = fma2(x0.x, wv.x, acc[e][0]);
                acc[e][0] = fma2(x0.y, wv.y, acc[e][0]);
                acc[e][1] = fma2(x1.x, wv.x, acc[e][1]);
                acc[e][1] = fma2(x1.y, wv.y, acc[e][1]);
                acc[e][2] = fma2(x2.x, wv.x, acc[e][2]);
                acc[e][2] = fma2(x2.y, wv.y, acc[e][2]);
                acc[e][3] = fma2(x3.x, wv.x, acc[e][3]);
                acc[e][3] = fma2(x3.y, wv.y, acc[e][3]);
            }
            x0 = n0; x1 = n1; x2 = n2; x3 = n3;
            idx = nidx;
        }
    } else {
        // Slow path: per-token weight bases (rare boundary quads).
        const ulonglong2* w0 = reinterpret_cast<const ulonglong2*>(We + (size_t)c0 * (E_EX * D_DIM));
        const ulonglong2* w1 = reinterpret_cast<const ulonglong2*>(We + (size_t)c1 * (E_EX * D_DIM));
        const ulonglong2* w2 = reinterpret_cast<const ulonglong2*>(We + (size_t)c2 * (E_EX * D_DIM));
        const ulonglong2* w3 = reinterpret_cast<const ulonglong2*>(We + (size_t)c3 * (E_EX * D_DIM));
        for (int it = 0; it < 16; ++it) {
            const int idx = s * 512 + it * 32 + lane;
            ulonglong2 x0 = __ldg(xr0 + idx);
            ulonglong2 x1 = __ldg(xr1 + idx);
            ulonglong2 x2 = __ldg(xr2 + idx);
            ulonglong2 x3 = __ldg(xr3 + idx);
#pragma unroll
            for (int e = 0; e < E_EX; ++e) {
                ulonglong2 a0 = __ldg(w0 + e * NU2 + idx);
                ulonglong2 a1 = __ldg(w1 + e * NU2 + idx);
                ulonglong2 a2 = __ldg(w2 + e * NU2 + idx);
                ulonglong2 a3 = __ldg(w3 + e * NU2 + idx);
                acc[e][0] = fma2(x0.x, a0.x, acc[e][0]);
                acc[e][0] = fma2(x0.y, a0.y, acc[e][0]);
                acc[e][1] = fma2(x1.x, a1.x, acc[e][1]);
                acc[e][1] = fma2(x1.y, a1.y, acc[e][1]);
                acc[e][2] = fma2(x2.x, a2.x, acc[e][2]);
                acc[e][2] = fma2(x2.y, a2.y, acc[e][2]);
                acc[e][3] = fma2(x3.x, a3.x, acc[e][3]);
                acc[e][3] = fma2(x3.y, a3.y, acc[e][3]);
            }
        }
    }

    // Reduce e-by-e (low register pressure).
#pragma unroll
    for (int e = 0; e < E_EX; ++e) {
        float r0 = sum2(acc[e][0]), r1 = sum2(acc[e][1]);
        float r2 = sum2(acc[e][2]), r3 = sum2(acc[e][3]);
#pragma unroll
        for (int d = 16; d >= 1; d >>= 1) {
            r0 += __shfl_xor_sync(0xffffffffu, r0, d);
            r1 += __shfl_xor_sync(0xffffffffu, r1, d);
            r2 += __shfl_xor_sync(0xffffffffu, r2, d);
            r3 += __shfl_xor_sync(0xffffffffu, r3, d);
        }
        if (lane == e * 4 + 0) s_part[s][qi][0][e] = r0;
        if (lane == e * 4 + 1) s_part[s][qi][1][e] = r1;
        if (lane == e * 4 + 2) s_part[s][qi][2][e] = r2;
        if (lane == e * 4 + 3) s_part[s][qi][3][e] = r3;
    }
    __syncthreads();

    // Combine splits + fetch expert ids: 128 threads = 16 tok x 8 e.
    if (threadIdx.x < 128) {
        const int tl = threadIdx.x >> 3;
        const int e  = threadIdx.x & 7;
        const int quad = tl >> 2, tt = tl & 3;
        s_logit[tl][e] = s_part[0][quad][tt][e] + s_part[1][quad][tt][e];
        s_eid[tl][e]   = read_eid(eids, s_cl[tl] * E_EX + e);
    }
    __syncthreads();

    // Scatter: 256 threads = 16 tokens x 16 float4 (full 64-col rows).
    {
        const int tl = threadIdx.x >> 4;
        const int q  = threadIdx.x & 15;
        const int tok = s_tok[tl];
        float v[4];
#pragma unroll
        for (int j = 0; j < 4; ++j) {
            const int col = q * 4 + j;
            float val = -FLT_MAX;              // == jnp.finfo(float32).min
#pragma unroll
            for (int e = 0; e < E_EX; ++e)
                val = (s_eid[tl][e] == col) ? s_logit[tl][e] : val;
            v[j] = val;
        }
        reinterpret_cast<float4*>(out + (size_t)tok * NTOT)[q] =
            make_float4(v[0], v[1], v[2], v[3]);
    }
}

extern "C" void kernel_launch(void* const* d_in, const int* in_sizes, int n_in,
                              void* d_out, int out_size) {
    const float* x    = (const float*)d_in[0];
    const float* Wc   = (const float*)d_in[1];
    const float* We   = (const float*)d_in[2];
    const void*  eids = d_in[3];
    float*       out  = (float*)d_out;

    const int D = in_sizes[2] / in_sizes[3];     // 4096
    const int T = in_sizes[0] / D;               // 8192
    (void)n_in; (void)out_size;

    zero_cnt_kernel<<<1, 32>>>();

    const int blocks = T / 16;           // 16 tokens per block
    cluster_kernel<<<blocks, 256>>>(x, Wc);
    order_kernel<<<C_CL, 256>>>();
    expert_kernel<<<blocks, 256>>>(x, We, eids, out);
}